// round 16
// baseline (speedup 1.0000x reference)
#include <cuda_runtime.h>
#include <cstdint>

// LWTA over groups of 4 consecutive fp32 on [4096, 8192] fp32.
// R16 experiment: TMA bulk-copy read front end. Each CTA streams a contiguous
// 128KB region as 8 x 16KB tiles via cp.async.bulk (UBLKCP) into a
// double-buffered smem staging area, paced by mbarriers; compute reads smem,
// stores go directly to global with .cg (write path unchanged from R11).
// Goal: present the DRAM controller with long sequential read bursts instead
// of finely interleaved per-warp sectors, to reduce row-miss/turnaround dead
// cycles (dram_active pinned at ~75% across all LDG-based variants).

#define NT     512
#define F4T    1024              // float4 per tile = 16KB
#define TILE_B 16384
#define TPC    8                 // tiles per CTA (contiguous region = 128KB)
#define NBLK   1024              // 8192 tiles total / TPC

__global__ void __launch_bounds__(NT) lwta_kernel(const float4* __restrict__ in,
                                                  float4* __restrict__ out) {
    __shared__ alignas(1024) float4 buf[2][F4T];   // 32KB staging
    __shared__ alignas(8) uint64_t mbar[2];

    const int tid = threadIdx.x;
    uint32_t mb0 = (uint32_t)__cvta_generic_to_shared(&mbar[0]);

    if (tid == 0) {
        asm volatile("mbarrier.init.shared.b64 [%0], 1;" :: "r"(mb0) : "memory");
        asm volatile("mbarrier.init.shared.b64 [%0], 1;" :: "r"(mb0 + 8) : "memory");
    }
    __syncthreads();

    const long t0 = (long)blockIdx.x * TPC;   // first tile index for this CTA

    // Prologue: fill both stages (tiles t0, t0+1)
    if (tid == 0) {
#pragma unroll
        for (int s = 0; s < 2; s++) {
            uint32_t mb  = mb0 + 8u * s;
            uint32_t dst = (uint32_t)__cvta_generic_to_shared(&buf[s][0]);
            const float4* src = in + (t0 + s) * F4T;
            asm volatile("mbarrier.arrive.expect_tx.shared.b64 _, [%0], %1;"
                         :: "r"(mb), "r"((uint32_t)TILE_B) : "memory");
            asm volatile("cp.async.bulk.shared::cta.global.mbarrier::complete_tx::bytes"
                         " [%0], [%1], %2, [%3];"
                         :: "r"(dst), "l"(src), "r"((uint32_t)TILE_B), "r"(mb)
                         : "memory");
        }
    }

    int ph0 = 0, ph1 = 0;

    for (int i = 0; i < TPC; i++) {
        const int s = i & 1;
        const uint32_t mb = mb0 + 8u * s;
        const int ph = s ? ph1 : ph0;

        // Wait for stage s full (acquire)
        uint32_t done;
        do {
            asm volatile("{\n\t.reg .pred p;\n\t"
                         "mbarrier.try_wait.parity.acquire.cta.shared::cta.b64 p, [%1], %2;\n\t"
                         "selp.b32 %0, 1, 0, p;\n\t}"
                         : "=r"(done) : "r"(mb), "r"(ph) : "memory");
        } while (!done);
        if (s) ph1 ^= 1; else ph0 ^= 1;

        // Compute 2 groups/thread from smem, store directly to global
        const long gbase = (t0 + i) * F4T;
#pragma unroll
        for (int k = 0; k < 2; k++) {
            float4 x = buf[s][tid + k * NT];
            // argmax, first-max-wins (strict >), matching jnp.argmax
            float m = x.x;
            int w = 0;
            if (x.y > m) { m = x.y; w = 1; }
            if (x.z > m) { m = x.z; w = 2; }
            if (x.w > m) { m = x.w; w = 3; }
            float4 r;
            r.x = (w == 0) ? x.x : 0.0f;
            r.y = (w == 1) ? x.y : 0.0f;
            r.z = (w == 2) ? x.z : 0.0f;
            r.w = (w == 3) ? x.w : 0.0f;
            __stcg(&out[gbase + tid + k * NT], r);
        }

        __syncthreads();   // all threads finished reading buf[s]

        // Refill stage s with tile i+2
        if (tid == 0 && i + 2 < TPC) {
            uint32_t dst = (uint32_t)__cvta_generic_to_shared(&buf[s][0]);
            const float4* src = in + (t0 + i + 2) * F4T;
            asm volatile("mbarrier.arrive.expect_tx.shared.b64 _, [%0], %1;"
                         :: "r"(mb), "r"((uint32_t)TILE_B) : "memory");
            asm volatile("cp.async.bulk.shared::cta.global.mbarrier::complete_tx::bytes"
                         " [%0], [%1], %2, [%3];"
                         :: "r"(dst), "l"(src), "r"((uint32_t)TILE_B), "r"(mb)
                         : "memory");
        }
    }
}

extern "C" void kernel_launch(void* const* d_in, const int* in_sizes, int n_in,
                              void* d_out, int out_size) {
    const float4* in = (const float4*)d_in[0];
    float4* out = (float4*)d_out;
    // 4096*8192 fp32 = 8388608 float4 groups = 8192 tiles of 1024; exact tiling.
    lwta_kernel<<<NBLK, NT>>>(in, out);
}